// round 2
// baseline (speedup 1.0000x reference)
#include <cuda_runtime.h>
#include <math.h>

#define Vv    20000
#define Ld    128
#define Dd    256
#define DEMOd 70
#define HIDd  1024
#define Nn    2048

#define ESTR  257                     // emb row stride (floats), +1 pad: conflict-free for both access patterns
#define EMB_F   (Ld * ESTR)           // 32896
#define REGION_F 16384                // aliased: Ms [256][32] (phase2) / scores [128][128] (phase3+)
#define TSH_F   4096                  // t_sh [8 warps][2 rows][256]
#define SMEM_F  (EMB_F + REGION_F + TSH_F + 128 /*times*/ + 128 /*w*/ + 128 /*a*/ + 256 /*u*/ + 128 /*codes*/)
#define SMEM_BYTES (SMEM_F * 4)       // 216,576 B < 227 KB limit

// device scratch (allocation-free rule: __device__ globals)
__device__ float g_M[Dd * Dd];
__device__ float g_t[(size_t)Nn * Ld * Dd];   // 256 MB; same-CTA produce/consume -> L2-resident
__device__ float g_repr[Nn * Dd];
__device__ float g_loss[Nn];

// ---------------------------------------------------------------------------
// Kernel 1: M = Wq @ Wk^T   (M[d][d'] = sum_e Wq[d][e] * Wk[d'][e])
// ---------------------------------------------------------------------------
__global__ void __launch_bounds__(256) k_M(const float* __restrict__ Wq,
                                           const float* __restrict__ Wk) {
    __shared__ float qrow[Dd];
    int d = blockIdx.x;
    for (int e = threadIdx.x; e < Dd; e += 256) qrow[e] = Wq[d * Dd + e];
    __syncthreads();
    int dp = threadIdx.x;
    const float* kr = Wk + dp * Dd;
    float acc = 0.f;
#pragma unroll 8
    for (int e = 0; e < Dd; e++) acc += qrow[e] * kr[e];
    g_M[d * Dd + dp] = acc;
}

// ---------------------------------------------------------------------------
// Kernel 2: per-sample fused attention + pooling + repr.  One CTA = one sample.
// ---------------------------------------------------------------------------
extern __shared__ float smem[];

__global__ void __launch_bounds__(256) k_main(
    const float* __restrict__ E, const float* __restrict__ Wv,
    const float* __restrict__ c_attn, const float* __restrict__ c_pool,
    const float* __restrict__ hist_times, const float* __restrict__ event_time,
    const int* __restrict__ codes, const int* __restrict__ lengths)
{
    const int n   = blockIdx.x;
    const int tid = threadIdx.x;
    const int len = lengths[n];

    float* emb    = smem;                       // [128][257]
    float* region = smem + EMB_F;               // Ms / scores alias
    float* t_sh   = region + REGION_F;          // [8][2][256]
    float* times  = t_sh + TSH_F;               // 128
    float* w_sh   = times + 128;                // 128
    float* a_sh   = w_sh + 128;                 // 128
    float* u_sh   = a_sh + 128;                 // 256
    int*   codes_sh = (int*)(u_sh + 256);       // 128

    if (tid < Ld) {
        codes_sh[tid] = codes[n * Ld + tid];
        times[tid]    = hist_times[n * Ld + tid];
    }
    __syncthreads();

    // ---- gather emb (rows l < len), float4 global loads, scalar smem stores
    for (int idx = tid; idx < len * 64; idx += 256) {
        int l = idx >> 6, f4 = idx & 63;
        float4 v = ((const float4*)(E + (size_t)codes_sh[l] * Dd))[f4];
        float* dst = emb + l * ESTR + f4 * 4;
        dst[0] = v.x; dst[1] = v.y; dst[2] = v.z; dst[3] = v.w;
    }
    __syncthreads();

    // ---- phase 2: t = emb @ M  (chunks of 32 cols of M; 4x4 register tiles)
    float* tg = g_t + (size_t)n * Ld * Dd;
    {
        float* Ms = region;                     // [256][32]
        const int colgrp = tid & 7;             // 8 col groups x 4 cols
        const int i0     = (tid >> 3) * 4;      // 32 row groups x 4 rows
        for (int ch = 0; ch < 8; ch++) {
#pragma unroll
            for (int k = 0; k < 32; k++) {      // load Ms: coalesced
                int f = tid + k * 256;
                Ms[f] = g_M[(f >> 5) * Dd + ch * 32 + (f & 31)];
            }
            __syncthreads();
            if (i0 < len) {
                float acc[4][4] = {};
#pragma unroll 4
                for (int d = 0; d < Dd; d++) {
                    float e0 = emb[(i0 + 0) * ESTR + d];
                    float e1 = emb[(i0 + 1) * ESTR + d];
                    float e2 = emb[(i0 + 2) * ESTR + d];
                    float e3 = emb[(i0 + 3) * ESTR + d];
                    float m0 = Ms[d * 32 + colgrp * 4 + 0];
                    float m1 = Ms[d * 32 + colgrp * 4 + 1];
                    float m2 = Ms[d * 32 + colgrp * 4 + 2];
                    float m3 = Ms[d * 32 + colgrp * 4 + 3];
                    acc[0][0] += e0 * m0; acc[0][1] += e0 * m1; acc[0][2] += e0 * m2; acc[0][3] += e0 * m3;
                    acc[1][0] += e1 * m0; acc[1][1] += e1 * m1; acc[1][2] += e1 * m2; acc[1][3] += e1 * m3;
                    acc[2][0] += e2 * m0; acc[2][1] += e2 * m1; acc[2][2] += e2 * m2; acc[2][3] += e2 * m3;
                    acc[3][0] += e3 * m0; acc[3][1] += e3 * m1; acc[3][2] += e3 * m2; acc[3][3] += e3 * m3;
                }
#pragma unroll
                for (int rr = 0; rr < 4; rr++) {
                    if (i0 + rr < len) {
                        float4 o = make_float4(acc[rr][0], acc[rr][1], acc[rr][2], acc[rr][3]);
                        *((float4*)(tg + (i0 + rr) * Dd + ch * 32 + colgrp * 4)) = o;
                    }
                }
            }
            __syncthreads();
        }
    }

    // ---- phase 3: scores = t @ emb^T /16 - c*dt, fused row softmax -> attn probs
    float* scores = region;                     // [128][128]
    {
        const float ca = c_attn[0];
        const int w = tid >> 5, lane = tid & 31;
        float* tw = t_sh + w * 512;
        for (int p = w; 2 * p < len; p += 8) {
            const int i0r = 2 * p;
            // cooperative load of up to 2 t-rows (float4, from L2-resident g_t)
            for (int q = lane; q < 128; q += 32) {
                int r = q >> 6, f4 = q & 63;
                if (i0r + r < len)
                    *((float4*)(tw + r * 256 + f4 * 4)) =
                        ((const float4*)(tg + (size_t)(i0r + r) * Dd))[f4];
            }
            __syncwarp();
            float acc[2][4] = {};
#pragma unroll 2
            for (int d = 0; d < Dd; d++) {
                float t0 = tw[d];
                float t1 = tw[256 + d];
#pragma unroll
                for (int k = 0; k < 4; k++) {
                    float e = emb[(lane + 32 * k) * ESTR + d];
                    acc[0][k] += t0 * e;
                    acc[1][k] += t1 * e;
                }
            }
#pragma unroll
            for (int r = 0; r < 2; r++) {
                int i = i0r + r;
                if (i < len) {
                    float ti = times[i];
                    float s[4]; float mx = -1e30f;
#pragma unroll
                    for (int k = 0; k < 4; k++) {
                        int j = lane + 32 * k;
                        s[k] = (j < len) ? acc[r][k] * 0.0625f - ca * fabsf(ti - times[j])
                                         : -1e30f;
                        mx = fmaxf(mx, s[k]);
                    }
                    for (int o = 16; o; o >>= 1) mx = fmaxf(mx, __shfl_xor_sync(0xffffffffu, mx, o));
                    float ex[4]; float sum = 0.f;
#pragma unroll
                    for (int k = 0; k < 4; k++) {
                        int j = lane + 32 * k;
                        ex[k] = (j < len) ? __expf(s[k] - mx) : 0.f;
                        sum += ex[k];
                    }
                    for (int o = 16; o; o >>= 1) sum += __shfl_xor_sync(0xffffffffu, sum, o);
                    float inv = 1.f / sum;
#pragma unroll
                    for (int k = 0; k < 4; k++) {
                        int j = lane + 32 * k;
                        if (j < len) scores[i * 128 + j] = ex[k] * inv;
                    }
                }
            }
            __syncwarp();   // protect t_sh reuse
        }
    }
    __syncthreads();

    // ---- phase 4: pooling weights w (warp 0), a = w@attn, u = a@emb, repr = u@Wv
    {
        const float cp = c_pool[0];
        const float ev = event_time[n];
        if (tid < 32) {
            int lane = tid;
            float s[4]; float mx = -1e30f;
#pragma unroll
            for (int k = 0; k < 4; k++) {
                int l = lane + 32 * k;
                s[k] = (l < len) ? -cp * (ev - times[l]) : -1e30f;
                mx = fmaxf(mx, s[k]);
            }
            for (int o = 16; o; o >>= 1) mx = fmaxf(mx, __shfl_xor_sync(0xffffffffu, mx, o));
            float ex[4]; float sum = 0.f;
#pragma unroll
            for (int k = 0; k < 4; k++) {
                int l = lane + 32 * k;
                ex[k] = (l < len) ? __expf(s[k] - mx) : 0.f;
                sum += ex[k];
            }
            for (int o = 16; o; o >>= 1) sum += __shfl_xor_sync(0xffffffffu, sum, o);
            float inv = 1.f / sum;
#pragma unroll
            for (int k = 0; k < 4; k++) {
                int l = lane + 32 * k;
                if (l < Ld) w_sh[l] = (l < len) ? ex[k] * inv : 0.f;
            }
        }
        __syncthreads();

        if (tid < 128) {
            int j = tid;
            float a = 0.f;
            if (j < len)
                for (int l = 0; l < len; l++) a += w_sh[l] * scores[l * 128 + j];
            a_sh[j] = (j < len) ? a : 0.f;
        }
        __syncthreads();

        {   // u_d
            int d = tid;
            float u = 0.f;
            for (int j = 0; j < len; j++) u += a_sh[j] * emb[j * ESTR + d];
            u_sh[d] = u;
        }
        __syncthreads();

        {   // repr[e] = sum_d u_d * Wv[d][e]
            int e = tid;
            float r = 0.f;
#pragma unroll 4
            for (int d = 0; d < Dd; d++) r += u_sh[d] * Wv[d * Dd + e];
            g_repr[n * Dd + e] = r;
        }
    }
}

// ---------------------------------------------------------------------------
// Kernel 3: per-sample MLP + stable BCE-with-logits (pos_weight=2)
// ---------------------------------------------------------------------------
__device__ __forceinline__ float log_sigmoid(float z) {
    return (z >= 0.f) ? -log1pf(expf(-z)) : z - log1pf(expf(z));
}

__global__ void __launch_bounds__(256) k_mlp(
    const float* __restrict__ W1, const float* __restrict__ b1,
    const float* __restrict__ W2, const float* __restrict__ b2,
    const float* __restrict__ demo, const float* __restrict__ labels)
{
    __shared__ float x_s[DEMOd + Dd];
    __shared__ float red[256];
    const int n = blockIdx.x, tid = threadIdx.x;

    if (tid < DEMOd) x_s[tid] = demo[n * DEMOd + tid];
    if (tid < Dd)    x_s[DEMOd + tid] = g_repr[n * Dd + tid];
    __syncthreads();

    float h[4];
#pragma unroll
    for (int j = 0; j < 4; j++) h[j] = b1[tid + 256 * j];
#pragma unroll 2
    for (int m = 0; m < DEMOd + Dd; m++) {
        float xv = x_s[m];
#pragma unroll
        for (int j = 0; j < 4; j++) h[j] += xv * W1[m * HIDd + tid + 256 * j];
    }
    float part = 0.f;
#pragma unroll
    for (int j = 0; j < 4; j++) part += fmaxf(h[j], 0.f) * W2[tid + 256 * j];
    red[tid] = part;
    __syncthreads();
    for (int s = 128; s > 0; s >>= 1) {
        if (tid < s) red[tid] += red[tid + s];
        __syncthreads();
    }
    if (tid == 0) {
        float z = red[0] + b2[0];
        float y = labels[n];
        g_loss[n] = -(2.0f * y * log_sigmoid(z) + (1.0f - y) * log_sigmoid(-z));
    }
}

// ---------------------------------------------------------------------------
// Kernel 4: deterministic reduce + regularization
// ---------------------------------------------------------------------------
__global__ void __launch_bounds__(256) k_red(const float* __restrict__ c_attn,
                                             const float* __restrict__ c_pool,
                                             float* __restrict__ out)
{
    __shared__ float red[256];
    int tid = threadIdx.x;
    float s = 0.f;
    for (int i = tid; i < Nn; i += 256) s += g_loss[i];
    red[tid] = s;
    __syncthreads();
    for (int k = 128; k > 0; k >>= 1) {
        if (tid < k) red[tid] += red[tid + k];
        __syncthreads();
    }
    if (tid == 0)
        out[0] = red[0] / (float)Nn + c_attn[0] * c_attn[0] + c_pool[0] * c_pool[0];
}

// ---------------------------------------------------------------------------
extern "C" void kernel_launch(void* const* d_in, const int* in_sizes, int n_in,
                              void* d_out, int out_size)
{
    const float* E          = (const float*)d_in[0];
    const float* Wq         = (const float*)d_in[1];
    const float* Wk         = (const float*)d_in[2];
    const float* Wv         = (const float*)d_in[3];
    const float* c_attn     = (const float*)d_in[4];
    const float* c_pool     = (const float*)d_in[5];
    const float* W1         = (const float*)d_in[6];
    const float* b1         = (const float*)d_in[7];
    const float* W2         = (const float*)d_in[8];
    const float* b2         = (const float*)d_in[9];
    const float* demo       = (const float*)d_in[10];
    const float* hist_times = (const float*)d_in[11];
    const float* event_time = (const float*)d_in[12];
    const float* labels     = (const float*)d_in[13];
    const int*   codes      = (const int*)d_in[14];
    const int*   lengths    = (const int*)d_in[15];

    cudaFuncSetAttribute(k_main, cudaFuncAttributeMaxDynamicSharedMemorySize, SMEM_BYTES);

    k_M   <<<Dd, 256>>>(Wq, Wk);
    k_main<<<Nn, 256, SMEM_BYTES>>>(E, Wv, c_attn, c_pool, hist_times, event_time,
                                    codes, lengths);
    k_mlp <<<Nn, 256>>>(W1, b1, W2, b2, demo, labels);
    k_red <<<1, 256>>>(c_attn, c_pool, (float*)d_out);
}

// round 3
// speedup vs baseline: 1.2061x; 1.2061x over previous
#include <cuda_runtime.h>
#include <math.h>

#define Vv    20000
#define Ld    128
#define Dd    256
#define DEMOd 70
#define HIDd  1024
#define Nn    2048

#define ESTR  260                     // emb row stride (floats): 16B-aligned rows, 260%32=4 keeps LDS.128 conflict-free
#define EMB_F   (Ld * ESTR)           // 33280
#define REGION_F 16384                // aliased: Ms [256][32] (phase2) / scores [128][128] (phase3+)
#define TSH_F   4096                  // t_sh [8 warps][2 rows][256]
#define SMEM_F  (EMB_F + REGION_F + TSH_F + 128 /*times*/ + 128 /*w*/ + 128 /*a*/ + 256 /*u*/ + 128 /*codes*/)
#define SMEM_BYTES (SMEM_F * 4)       // 218,112 B < 227 KB limit

// device scratch (allocation-free rule: __device__ globals)
__device__ float g_M[Dd * Dd];
__device__ float g_t[(size_t)Nn * Ld * Dd];   // same-CTA produce/consume -> L2-resident window
__device__ float g_repr[Nn * Dd];
__device__ float g_loss[Nn];

// ---------------------------------------------------------------------------
// Kernel 1: M = Wq @ Wk^T   (M[d][d'] = sum_e Wq[d][e] * Wk[d'][e])
// ---------------------------------------------------------------------------
__global__ void __launch_bounds__(256) k_M(const float* __restrict__ Wq,
                                           const float* __restrict__ Wk) {
    __shared__ float qrow[Dd];
    int d = blockIdx.x;
    for (int e = threadIdx.x; e < Dd; e += 256) qrow[e] = Wq[d * Dd + e];
    __syncthreads();
    int dp = threadIdx.x;
    const float* kr = Wk + dp * Dd;
    float acc = 0.f;
#pragma unroll 8
    for (int e = 0; e < Dd; e++) acc += qrow[e] * kr[e];
    g_M[d * Dd + dp] = acc;
}

// ---------------------------------------------------------------------------
// Kernel 2: per-sample fused attention + pooling + repr.  One CTA = one sample.
// ---------------------------------------------------------------------------
extern __shared__ float smem[];

__global__ void __launch_bounds__(256) k_main(
    const float* __restrict__ E, const float* __restrict__ Wv,
    const float* __restrict__ c_attn, const float* __restrict__ c_pool,
    const float* __restrict__ hist_times, const float* __restrict__ event_time,
    const int* __restrict__ codes, const int* __restrict__ lengths)
{
    const int n   = blockIdx.x;
    const int tid = threadIdx.x;
    const int len = lengths[n];

    float* emb    = smem;                       // [128][260]
    float* region = smem + EMB_F;               // Ms / scores alias
    float* t_sh   = region + REGION_F;          // [8][2][256]
    float* times  = t_sh + TSH_F;               // 128
    float* w_sh   = times + 128;                // 128
    float* a_sh   = w_sh + 128;                 // 128
    float* u_sh   = a_sh + 128;                 // 256
    int*   codes_sh = (int*)(u_sh + 256);       // 128

    if (tid < Ld) {
        codes_sh[tid] = codes[n * Ld + tid];
        times[tid]    = hist_times[n * Ld + tid];
    }
    __syncthreads();

    // ---- gather emb (rows l < len): float4 loads AND float4 smem stores
    for (int idx = tid; idx < len * 64; idx += 256) {
        int l = idx >> 6, f4 = idx & 63;
        float4 v = ((const float4*)(E + (size_t)codes_sh[l] * Dd))[f4];
        *((float4*)(emb + l * ESTR + f4 * 4)) = v;
    }
    __syncthreads();

    // ---- phase 2: t = emb @ M  (8 chunks of 32 M-cols; 4x4 register tiles, LDS.128)
    float* tg = g_t + (size_t)n * Ld * Dd;
    {
        float* Ms = region;                     // [256][32]
        const int colgrp = tid & 7;             // 8 col groups x 4 cols
        const int i0     = (tid >> 3) * 4;      // 32 row groups x 4 rows
        for (int ch = 0; ch < 8; ch++) {
#pragma unroll
            for (int k = 0; k < 32; k++) {      // load Ms: coalesced
                int f = tid + k * 256;
                Ms[f] = g_M[(f >> 5) * Dd + ch * 32 + (f & 31)];
            }
            __syncthreads();
            if (i0 < len) {
                float acc[4][4] = {};
                const float* ms_base = Ms + colgrp * 4;
#pragma unroll 2
                for (int d4 = 0; d4 < 64; d4++) {
                    float4 m0 = *((const float4*)(ms_base + (d4 * 4 + 0) * 32));
                    float4 m1 = *((const float4*)(ms_base + (d4 * 4 + 1) * 32));
                    float4 m2 = *((const float4*)(ms_base + (d4 * 4 + 2) * 32));
                    float4 m3 = *((const float4*)(ms_base + (d4 * 4 + 3) * 32));
#pragma unroll
                    for (int r = 0; r < 4; r++) {
                        float4 e = *((const float4*)(emb + (i0 + r) * ESTR + d4 * 4));
                        acc[r][0] += e.x * m0.x + e.y * m1.x + e.z * m2.x + e.w * m3.x;
                        acc[r][1] += e.x * m0.y + e.y * m1.y + e.z * m2.y + e.w * m3.y;
                        acc[r][2] += e.x * m0.z + e.y * m1.z + e.z * m2.z + e.w * m3.z;
                        acc[r][3] += e.x * m0.w + e.y * m1.w + e.z * m2.w + e.w * m3.w;
                    }
                }
#pragma unroll
                for (int rr = 0; rr < 4; rr++) {
                    if (i0 + rr < len) {
                        float4 o = make_float4(acc[rr][0], acc[rr][1], acc[rr][2], acc[rr][3]);
                        *((float4*)(tg + (i0 + rr) * Dd + ch * 32 + colgrp * 4)) = o;
                    }
                }
            }
            __syncthreads();
        }
    }

    // ---- phase 3: scores = t @ emb^T /16 - c*dt, fused row softmax -> attn probs
    float* scores = region;                     // [128][128]
    {
        const float ca = c_attn[0];
        const int w = tid >> 5, lane = tid & 31;
        float* tw = t_sh + w * 512;
        for (int p = w; 2 * p < len; p += 8) {
            const int i0r = 2 * p;
            // cooperative load of up to 2 t-rows (float4, from L2-resident g_t)
            for (int q = lane; q < 128; q += 32) {
                int r = q >> 6, f4 = q & 63;
                if (i0r + r < len)
                    *((float4*)(tw + r * 256 + f4 * 4)) =
                        ((const float4*)(tg + (size_t)(i0r + r) * Dd))[f4];
            }
            __syncwarp();
            float acc[2][4] = {};
#pragma unroll 2
            for (int d4 = 0; d4 < 64; d4++) {
                float4 t0 = ((const float4*)tw)[d4];
                float4 t1 = ((const float4*)(tw + 256))[d4];
#pragma unroll
                for (int k = 0; k < 4; k++) {
                    float4 e = *((const float4*)(emb + (lane + 32 * k) * ESTR + d4 * 4));
                    acc[0][k] += t0.x * e.x + t0.y * e.y + t0.z * e.z + t0.w * e.w;
                    acc[1][k] += t1.x * e.x + t1.y * e.y + t1.z * e.z + t1.w * e.w;
                }
            }
#pragma unroll
            for (int r = 0; r < 2; r++) {
                int i = i0r + r;
                if (i < len) {
                    float ti = times[i];
                    float s[4]; float mx = -1e30f;
#pragma unroll
                    for (int k = 0; k < 4; k++) {
                        int j = lane + 32 * k;
                        s[k] = (j < len) ? acc[r][k] * 0.0625f - ca * fabsf(ti - times[j])
                                         : -1e30f;
                        mx = fmaxf(mx, s[k]);
                    }
                    for (int o = 16; o; o >>= 1) mx = fmaxf(mx, __shfl_xor_sync(0xffffffffu, mx, o));
                    float ex[4]; float sum = 0.f;
#pragma unroll
                    for (int k = 0; k < 4; k++) {
                        int j = lane + 32 * k;
                        ex[k] = (j < len) ? __expf(s[k] - mx) : 0.f;
                        sum += ex[k];
                    }
                    for (int o = 16; o; o >>= 1) sum += __shfl_xor_sync(0xffffffffu, sum, o);
                    float inv = 1.f / sum;
#pragma unroll
                    for (int k = 0; k < 4; k++) {
                        int j = lane + 32 * k;
                        if (j < len) scores[i * 128 + j] = ex[k] * inv;
                    }
                }
            }
            __syncwarp();   // protect t_sh reuse
        }
    }
    __syncthreads();

    // ---- phase 4: pooling weights w (warp 0), a = w@attn, u = a@emb, repr = u@Wv
    {
        const float cp = c_pool[0];
        const float ev = event_time[n];
        if (tid < 32) {
            int lane = tid;
            float s[4]; float mx = -1e30f;
#pragma unroll
            for (int k = 0; k < 4; k++) {
                int l = lane + 32 * k;
                s[k] = (l < len) ? -cp * (ev - times[l]) : -1e30f;
                mx = fmaxf(mx, s[k]);
            }
            for (int o = 16; o; o >>= 1) mx = fmaxf(mx, __shfl_xor_sync(0xffffffffu, mx, o));
            float ex[4]; float sum = 0.f;
#pragma unroll
            for (int k = 0; k < 4; k++) {
                int l = lane + 32 * k;
                ex[k] = (l < len) ? __expf(s[k] - mx) : 0.f;
                sum += ex[k];
            }
            for (int o = 16; o; o >>= 1) sum += __shfl_xor_sync(0xffffffffu, sum, o);
            float inv = 1.f / sum;
#pragma unroll
            for (int k = 0; k < 4; k++) {
                int l = lane + 32 * k;
                if (l < Ld) w_sh[l] = (l < len) ? ex[k] * inv : 0.f;
            }
        }
        __syncthreads();

        if (tid < 128) {
            int j = tid;
            float a = 0.f;
            if (j < len)
                for (int l = 0; l < len; l++) a += w_sh[l] * scores[l * 128 + j];
            a_sh[j] = (j < len) ? a : 0.f;
        }
        __syncthreads();

        {   // u_d
            int d = tid;
            float u = 0.f;
            for (int j = 0; j < len; j++) u += a_sh[j] * emb[j * ESTR + d];
            u_sh[d] = u;
        }
        __syncthreads();

        {   // repr[e] = sum_d u_d * Wv[d][e]
            int e = tid;
            float r = 0.f;
#pragma unroll 4
            for (int d = 0; d < Dd; d++) r += u_sh[d] * Wv[d * Dd + e];
            g_repr[n * Dd + e] = r;
        }
    }
}

// ---------------------------------------------------------------------------
// Kernel 3: tiled MLP (16 samples/CTA, W1 read once per CTA) + stable BCE
// ---------------------------------------------------------------------------
#define TILE 16
#define XF   (DEMOd + Dd)    // 326

__device__ __forceinline__ float log_sigmoid(float z) {
    return (z >= 0.f) ? -log1pf(expf(-z)) : z - log1pf(expf(z));
}

__global__ void __launch_bounds__(256) k_mlp(
    const float* __restrict__ W1, const float* __restrict__ b1,
    const float* __restrict__ W2, const float* __restrict__ b2,
    const float* __restrict__ demo, const float* __restrict__ labels)
{
    __shared__ float x_s[XF * TILE];        // [m][s]
    __shared__ float red[TILE * 256];       // [s][tid]
    const int n0 = blockIdx.x * TILE, tid = threadIdx.x;

    for (int idx = tid; idx < XF * TILE; idx += 256) {
        int m = idx >> 4, s = idx & 15;
        x_s[idx] = (m < DEMOd) ? demo[(n0 + s) * DEMOd + m]
                               : g_repr[(n0 + s) * Dd + (m - DEMOd)];
    }
    __syncthreads();

    float h[4][TILE];
#pragma unroll
    for (int k = 0; k < 4; k++) {
        float b = b1[tid + 256 * k];
#pragma unroll
        for (int s = 0; s < TILE; s++) h[k][s] = b;
    }
#pragma unroll 2
    for (int m = 0; m < XF; m++) {
        float w1[4];
#pragma unroll
        for (int k = 0; k < 4; k++) w1[k] = W1[m * HIDd + tid + 256 * k];
        float4 x0 = ((const float4*)(x_s + m * TILE))[0];
        float4 x1 = ((const float4*)(x_s + m * TILE))[1];
        float4 x2 = ((const float4*)(x_s + m * TILE))[2];
        float4 x3 = ((const float4*)(x_s + m * TILE))[3];
        float xv[TILE] = {x0.x, x0.y, x0.z, x0.w, x1.x, x1.y, x1.z, x1.w,
                          x2.x, x2.y, x2.z, x2.w, x3.x, x3.y, x3.z, x3.w};
#pragma unroll
        for (int k = 0; k < 4; k++)
#pragma unroll
            for (int s = 0; s < TILE; s++) h[k][s] += w1[k] * xv[s];
    }

    float part[TILE];
#pragma unroll
    for (int s = 0; s < TILE; s++) part[s] = 0.f;
#pragma unroll
    for (int k = 0; k < 4; k++) {
        float w2 = W2[tid + 256 * k];
#pragma unroll
        for (int s = 0; s < TILE; s++) part[s] += fmaxf(h[k][s], 0.f) * w2;
    }
#pragma unroll
    for (int s = 0; s < TILE; s++) red[s * 256 + tid] = part[s];
    __syncthreads();
    for (int stride = 128; stride > 0; stride >>= 1) {
        if (tid < stride)
#pragma unroll
            for (int s = 0; s < TILE; s++)
                red[s * 256 + tid] += red[s * 256 + tid + stride];
        __syncthreads();
    }
    if (tid < TILE) {
        float z = red[tid * 256] + b2[0];
        float y = labels[n0 + tid];
        g_loss[n0 + tid] = -(2.0f * y * log_sigmoid(z) + (1.0f - y) * log_sigmoid(-z));
    }
}

// ---------------------------------------------------------------------------
// Kernel 4: deterministic reduce + regularization
// ---------------------------------------------------------------------------
__global__ void __launch_bounds__(256) k_red(const float* __restrict__ c_attn,
                                             const float* __restrict__ c_pool,
                                             float* __restrict__ out)
{
    __shared__ float red[256];
    int tid = threadIdx.x;
    float s = 0.f;
    for (int i = tid; i < Nn; i += 256) s += g_loss[i];
    red[tid] = s;
    __syncthreads();
    for (int k = 128; k > 0; k >>= 1) {
        if (tid < k) red[tid] += red[tid + k];
        __syncthreads();
    }
    if (tid == 0)
        out[0] = red[0] / (float)Nn + c_attn[0] * c_attn[0] + c_pool[0] * c_pool[0];
}

// ---------------------------------------------------------------------------
extern "C" void kernel_launch(void* const* d_in, const int* in_sizes, int n_in,
                              void* d_out, int out_size)
{
    const float* E          = (const float*)d_in[0];
    const float* Wq         = (const float*)d_in[1];
    const float* Wk         = (const float*)d_in[2];
    const float* Wv         = (const float*)d_in[3];
    const float* c_attn     = (const float*)d_in[4];
    const float* c_pool     = (const float*)d_in[5];
    const float* W1         = (const float*)d_in[6];
    const float* b1         = (const float*)d_in[7];
    const float* W2         = (const float*)d_in[8];
    const float* b2         = (const float*)d_in[9];
    const float* demo       = (const float*)d_in[10];
    const float* hist_times = (const float*)d_in[11];
    const float* event_time = (const float*)d_in[12];
    const float* labels     = (const float*)d_in[13];
    const int*   codes      = (const int*)d_in[14];
    const int*   lengths    = (const int*)d_in[15];

    cudaFuncSetAttribute(k_main, cudaFuncAttributeMaxDynamicSharedMemorySize, SMEM_BYTES);

    k_M   <<<Dd, 256>>>(Wq, Wk);
    k_main<<<Nn, 256, SMEM_BYTES>>>(E, Wv, c_attn, c_pool, hist_times, event_time,
                                    codes, lengths);
    k_mlp <<<Nn / TILE, 256>>>(W1, b1, W2, b2, demo, labels);
    k_red <<<1, 256>>>(c_attn, c_pool, (float*)d_out);
}